// round 1
// baseline (speedup 1.0000x reference)
#include <cuda_runtime.h>

// Problem constants (fixed by setup_inputs):
//   x:      (4, 64, 128, 128) fp32
//   weight: (4, 576, 128, 128) fp32  (9 taps per channel, tap k strided by H*W)
//   steps = min(8, 128) = 8
#define NIMG 256          // n*c = 4*64 independent 128x128 images
#define H 128
#define W 128
#define IMG (H * W)       // 16384
#define STEPS 8

// Ping-pong scratch (16 MB). __device__ global: allowed (no cudaMalloc).
__device__ float g_scratch[NIMG * IMG];

__global__ __launch_bounds__(256)
void diffusion_step_kernel(const float* __restrict__ xin_ext,
                           const float* __restrict__ wgt,
                           float* __restrict__ xout_ext,
                           int in_scratch, int out_scratch)
{
    const float* __restrict__ xin  = in_scratch  ? (const float*)g_scratch : xin_ext;
    float* __restrict__ xout       = out_scratch ? (float*)g_scratch       : xout_ext;

    // One thread = 4 consecutive w outputs (one float4).
    // Total threads: NIMG * H * (W/4) = 256 * 128 * 32 = 1,048,576
    int idx = blockIdx.x * blockDim.x + threadIdx.x;
    int w4  = idx & 31;          // float4 index within row
    int h   = (idx >> 5) & 127;
    int img = idx >> 12;         // 0..255
    int w0  = w4 << 2;

    const float* __restrict__ xb = xin + img * IMG;
    const float* __restrict__ wb = wgt + (size_t)img * 9 * IMG + h * W + w0;

    // --- load the 9 weight taps (coalesced float4 per tap, taps strided by IMG)
    float4 tap[9];
#pragma unroll
    for (int k = 0; k < 9; k++)
        tap[k] = __ldg(reinterpret_cast<const float4*>(wb + k * IMG));

    // --- fused normalization: a[k][lane] = |w_k|; inv[lane] = 1/sum_k a[k]
    float a[9][4];
#pragma unroll
    for (int k = 0; k < 9; k++) {
        a[k][0] = fabsf(tap[k].x);
        a[k][1] = fabsf(tap[k].y);
        a[k][2] = fabsf(tap[k].z);
        a[k][3] = fabsf(tap[k].w);
    }
    float inv[4];
#pragma unroll
    for (int l = 0; l < 4; l++) {
        float s = 0.f;
#pragma unroll
        for (int k = 0; k < 9; k++) s += a[k][l];
        inv[l] = __fdividef(1.0f, s);
    }

    // --- load x neighborhood: rows h-1..h+1, cols w0-1..w0+4 (zero pad OOB)
    float xr[3][6];
#pragma unroll
    for (int r = 0; r < 3; r++) {
        int hh = h + r - 1;
        bool hv = ((unsigned)hh < (unsigned)H);
        const float* row = xb + hh * W;
#pragma unroll
        for (int j = 0; j < 6; j++) {
            int ww = w0 - 1 + j;
            xr[r][j] = (hv && (unsigned)ww < (unsigned)W) ? __ldg(row + ww) : 0.f;
        }
    }

    // --- stencil: out[l] = (sum_k a[k]*x_shift) * inv   (== sum (a/s)*x)
    float4 out;
    float* outp = &out.x;
#pragma unroll
    for (int l = 0; l < 4; l++) {
        float acc = 0.f;
#pragma unroll
        for (int ki = 0; ki < 3; ki++)
#pragma unroll
            for (int kj = 0; kj < 3; kj++)
                acc = fmaf(a[ki * 3 + kj][l], xr[ki][l + kj], acc);
        outp[l] = acc * inv[l];
    }

    *reinterpret_cast<float4*>(xout + img * IMG + h * W + w0) = out;
}

extern "C" void kernel_launch(void* const* d_in, const int* in_sizes, int n_in,
                              void* d_out, int out_size)
{
    const float* x   = (const float*)d_in[0];
    const float* wgt = (const float*)d_in[1];
    float* out       = (float*)d_out;

    const int total_threads = NIMG * H * (W / 4);  // 1,048,576
    const int block = 256;
    const int grid  = total_threads / block;       // 4096

    // Ping-pong: step0 x->scratch, step1 scratch->out, step2 out->scratch, ...
    // step7 (odd) -> out. Final result lands in d_out.
    const float* src = x;
    int src_is_scratch = 0;
    for (int i = 0; i < STEPS; i++) {
        int dst_is_scratch = (i % 2 == 0) ? 1 : 0;
        float* dst = out;  // actual pointer only used when not scratch
        diffusion_step_kernel<<<grid, block>>>(src, wgt, dst,
                                               src_is_scratch, dst_is_scratch);
        src = dst;                 // external pointer for next step (if used)
        src_is_scratch = dst_is_scratch;
    }
}

// round 2
// speedup vs baseline: 2.6760x; 2.6760x over previous
#include <cuda_runtime.h>

// x:      (4, 64, 128, 128) fp32  -> 256 independent 128x128 images
// weight: (4, 576, 128, 128) fp32 -> 9 taps per channel, tap k strided by H*W
// steps = min(8, 128) = 8
//
// Strategy: fuse all 8 diffusion steps in ONE kernel.
//   - Tile: 16 output rows x 128 cols. Region: 32 rows (halo 8 top/bottom),
//     full width (no horizontal halo).
//   - Each CTA (1024 thr = 32 warps): warp w owns region row w, lane l owns
//     cols 4l..4l+3 (one float4).
//   - Weights: loaded from DRAM ONCE, normalized, kept in registers
//     (9 taps x 4 lanes = 36 regs). Out-of-image rows get zero weights ->
//     their pixels stay 0 forever (matches per-step zero padding).
//   - x: SMEM ping-pong, 1 barrier per step. Horizontal neighbors via shfl
//     with exact zero at image edges (lanes 0/31).
//   - Halo validity: after step s, smem rows [s+1, 32-s] are exact; after 8
//     steps rows 9..24 (warps 8..23) are exact = the 16 output rows.

#define H      128
#define W      128
#define IMG    (H * W)
#define STEPS  8
#define TH     16          // output rows per tile
#define SROWS  34          // 32 region rows + 2 guard rows
#define NIMG   256

__global__ __launch_bounds__(1024, 1)
void diffusion_fused_kernel(const float* __restrict__ x,
                            const float* __restrict__ wgt,
                            float* __restrict__ out)
{
    __shared__ float buf[2][SROWS][W];

    const int tid  = threadIdx.x;
    const int lane = tid & 31;
    const int warp = tid >> 5;                 // 0..31, smem row = warp+1
    const int img  = blockIdx.x >> 3;          // 0..255
    const int t0   = (blockIdx.x & 7) * TH;    // first output row of tile
    const int grow = t0 - 8 + warp;            // global row owned by this warp
    const bool rv  = ((unsigned)grow < (unsigned)H);
    const int col0 = lane << 2;

    // Zero the guard rows (never written again; keeps all smem reads in-bounds;
    // any value here only corrupts rows outside the proven-valid band).
    if (warp == 0) {
        *(float4*)&buf[0][0][col0] = make_float4(0.f, 0.f, 0.f, 0.f);
        *(float4*)&buf[1][0][col0] = make_float4(0.f, 0.f, 0.f, 0.f);
    }
    if (warp == 31) {
        *(float4*)&buf[0][SROWS - 1][col0] = make_float4(0.f, 0.f, 0.f, 0.f);
        *(float4*)&buf[1][SROWS - 1][col0] = make_float4(0.f, 0.f, 0.f, 0.f);
    }

    // Load x region row (zero-filled outside the image).
    float4 xv = make_float4(0.f, 0.f, 0.f, 0.f);
    if (rv) xv = *(const float4*)(x + img * IMG + grow * W + col0);
    *(float4*)&buf[0][warp + 1][col0] = xv;

    // Load 9 weight taps for our 4 pixels, normalize: a[k] = |w_k| / sum|w|.
    // Out-of-image rows -> all-zero weights -> pixel output is always 0.
    float a[9][4];
#pragma unroll
    for (int k = 0; k < 9; k++) {
        a[k][0] = 0.f; a[k][1] = 0.f; a[k][2] = 0.f; a[k][3] = 0.f;
    }
    if (rv) {
        const float* wb = wgt + (size_t)img * 9 * IMG + grow * W + col0;
        float s0 = 0.f, s1 = 0.f, s2 = 0.f, s3 = 0.f;
#pragma unroll
        for (int k = 0; k < 9; k++) {
            float4 t = __ldg(reinterpret_cast<const float4*>(wb + (size_t)k * IMG));
            a[k][0] = fabsf(t.x); a[k][1] = fabsf(t.y);
            a[k][2] = fabsf(t.z); a[k][3] = fabsf(t.w);
            s0 += a[k][0]; s1 += a[k][1]; s2 += a[k][2]; s3 += a[k][3];
        }
        const float i0 = (s0 > 0.f) ? __fdividef(1.f, s0) : 0.f;
        const float i1 = (s1 > 0.f) ? __fdividef(1.f, s1) : 0.f;
        const float i2 = (s2 > 0.f) ? __fdividef(1.f, s2) : 0.f;
        const float i3 = (s3 > 0.f) ? __fdividef(1.f, s3) : 0.f;
#pragma unroll
        for (int k = 0; k < 9; k++) {
            a[k][0] *= i0; a[k][1] *= i1; a[k][2] *= i2; a[k][3] *= i3;
        }
    }
    __syncthreads();

    const int r = warp + 1;
    float acc0 = 0.f, acc1 = 0.f, acc2 = 0.f, acc3 = 0.f;

#pragma unroll
    for (int s = 0; s < STEPS; s++) {
        const float (*cur)[W] = buf[s & 1];
        acc0 = 0.f; acc1 = 0.f; acc2 = 0.f; acc3 = 0.f;
#pragma unroll
        for (int dr = 0; dr < 3; dr++) {
            float4 v = *(const float4*)&cur[r - 1 + dr][col0];
            float xl = __shfl_up_sync(0xffffffffu, v.w, 1);
            float xr = __shfl_down_sync(0xffffffffu, v.x, 1);
            if (lane == 0)  xl = 0.f;   // exact image boundary (col -1)
            if (lane == 31) xr = 0.f;   // exact image boundary (col 128)
            const float a0 = a[dr * 3 + 0][0], b0 = a[dr * 3 + 1][0], c0 = a[dr * 3 + 2][0];
            const float a1 = a[dr * 3 + 0][1], b1 = a[dr * 3 + 1][1], c1 = a[dr * 3 + 2][1];
            const float a2 = a[dr * 3 + 0][2], b2 = a[dr * 3 + 1][2], c2 = a[dr * 3 + 2][2];
            const float a3 = a[dr * 3 + 0][3], b3 = a[dr * 3 + 1][3], c3 = a[dr * 3 + 2][3];
            acc0 = fmaf(a0, xl,  fmaf(b0, v.x, fmaf(c0, v.y, acc0)));
            acc1 = fmaf(a1, v.x, fmaf(b1, v.y, fmaf(c1, v.z, acc1)));
            acc2 = fmaf(a2, v.y, fmaf(b2, v.z, fmaf(c2, v.w, acc2)));
            acc3 = fmaf(a3, v.z, fmaf(b3, v.w, fmaf(c3, xr,  acc3)));
        }
        if (s < STEPS - 1) {
            float (*nxt)[W] = buf[(s + 1) & 1];
            // One barrier per step is sufficient: everyone's reads of `cur`
            // complete before this barrier; next step writes `cur`.
            *(float4*)&nxt[r][col0] = make_float4(acc0, acc1, acc2, acc3);
            __syncthreads();
        }
    }

    // Warps 8..23 hold the exact 16 output rows (global rows t0..t0+15).
    if (warp >= 8 && warp < 24) {
        *(float4*)(out + img * IMG + (t0 + warp - 8) * W + col0) =
            make_float4(acc0, acc1, acc2, acc3);
    }
}

extern "C" void kernel_launch(void* const* d_in, const int* in_sizes, int n_in,
                              void* d_out, int out_size)
{
    const float* x   = (const float*)d_in[0];
    const float* wgt = (const float*)d_in[1];
    float* out       = (float*)d_out;

    const int grid = NIMG * (H / TH);   // 256 * 8 = 2048 tiles
    diffusion_fused_kernel<<<grid, 1024>>>(x, wgt, out);
}

// round 3
// speedup vs baseline: 3.7724x; 1.4097x over previous
#include <cuda_runtime.h>

// x:      (4, 64, 128, 128) fp32  -> 256 independent 128x128 images
// weight: (4, 576, 128, 128) fp32 -> 9 taps per channel, tap k strided by H*W
// steps = 8 (min(max_step=8, 128))
//
// Persistent-CTA, fully fused 8-step diffusion:
//  - grid = #SMs, each CTA processes tiles t = bid, bid+grid, ... (2048 tiles:
//    256 images x 8 tiles of 16 output rows; region = 32 rows, full width).
//  - Weights+x for the NEXT tile are prefetched into SMEM staging with
//    cp.async.bulk + mbarrier while the current tile's 8 steps run.
//  - CTA = 512 threads (16 warps). Warp g owns region rows 2g, 2g+1; lane l
//    owns cols 4l..4l+3. Own-row values live in registers across steps; smem
//    ping-pong only publishes rows to vertical neighbors (1W+1R per row/step).
//  - Normalized weights live in registers as packed f32x2 pairs; the stencil
//    runs on fma.rn.f32x2 (2 FMAs/instr). Image left/right zero-padding is
//    folded into lane-0/lane-31 weight constants (no predicates in the loop).
//  - Validity: region rows s..31-s exact after step s => rows 8..23 exact
//    after 8 steps = the 16 output rows. Out-of-image rows get zero weights
//    and zero init, so they stay 0 (matches zero padding).

#define H      128
#define W      128
#define IMG    (H * W)
#define STEPS  8
#define TH     16
#define NT     2048
#define SROWS  34
#define RROWS  32

#define OFF_MBAR 0
#define OFF_BUF  1024
#define OFF_WS   (OFF_BUF + 2 * SROWS * W * 4)   // 1024 + 34816  = 35840
#define OFF_XS   (OFF_WS + 9 * RROWS * W * 4)    // + 147456      = 183296
#define SMEM_TOTAL (OFF_XS + RROWS * W * 4)      // + 16384       = 199680

typedef unsigned long long u64;
typedef unsigned int u32;

__device__ __forceinline__ u32 s2u(const void* p) {
    u32 a;
    asm("{ .reg .u64 t; cvta.to.shared.u64 t, %1; cvt.u32.u64 %0, t; }"
        : "=r"(a) : "l"(p));
    return a;
}
__device__ __forceinline__ u64 pk(float lo, float hi) {
    u64 r; asm("mov.b64 %0, {%1,%2};" : "=l"(r) : "f"(lo), "f"(hi)); return r;
}
__device__ __forceinline__ void upk(u64 v, float& lo, float& hi) {
    asm("mov.b64 {%0,%1}, %2;" : "=f"(lo), "=f"(hi) : "l"(v));
}
__device__ __forceinline__ void fma2(u64& d, u64 a, u64 b) {
    asm("fma.rn.f32x2 %0, %1, %2, %0;" : "+l"(d) : "l"(a), "l"(b));
}
__device__ __forceinline__ float shup(float v) { return __shfl_up_sync(0xffffffffu, v, 1); }
__device__ __forceinline__ float shdn(float v) { return __shfl_down_sync(0xffffffffu, v, 1); }

__device__ __forceinline__ void mbar_wait(u32 mbar, u32 parity) {
    asm volatile(
        "{\n\t.reg .pred P;\n\t"
        "W_%=:\n\t"
        "mbarrier.try_wait.parity.shared::cta.b64 P, [%0], %1, 0x989680;\n\t"
        "@P bra.uni D_%=;\n\t"
        "bra.uni W_%=;\n\t"
        "D_%=:\n\t}"
        :: "r"(mbar), "r"(parity) : "memory");
}
__device__ __forceinline__ void bulk_g2s(u32 dst, const void* src, u32 bytes, u32 mbar) {
    asm volatile(
        "cp.async.bulk.shared::cluster.global.mbarrier::complete_tx::bytes "
        "[%0], [%1], %2, [%3];"
        :: "r"(dst), "l"(src), "r"(bytes), "r"(mbar) : "memory");
}

// 5 packed horizontal operands of one source row (xl,x0,x1,x2,x3,xr)
struct P5 { u64 p0, p1, p2, p3, p4; };
__device__ __forceinline__ P5 mkP(float xl, float x0, float x1, float x2,
                                  float x3, float xr) {
    P5 p;
    p.p0 = pk(xl, x0); p.p1 = pk(x0, x1); p.p2 = pk(x1, x2);
    p.p3 = pk(x2, x3); p.p4 = pk(x3, xr);
    return p;
}
// accumulate one vertical tap row: w = {L01,C01,R01,L23,C23,R23}
__device__ __forceinline__ void accrow(u64& n01, u64& n23, const u64* w, const P5& p) {
    fma2(n01, w[0], p.p0); fma2(n01, w[1], p.p1); fma2(n01, w[2], p.p2);
    fma2(n23, w[3], p.p2); fma2(n23, w[4], p.p3); fma2(n23, w[5], p.p4);
}

__device__ __forceinline__ void issue_prefetch(int t, const float* x, const float* wgt,
                                               u32 ws, u32 xs, u32 mbar) {
    const int img = t >> 3;
    const int t0  = (t & 7) * TH;
    const int rlo = (t0 - 8 < 0) ? 0 : (t0 - 8);
    const int rhi = (t0 + 24 > H) ? H : (t0 + 24);
    const int nrows = rhi - rlo;
    const int droff = rlo - (t0 - 8);
    const u32 bytes = (u32)nrows * (W * 4);
    asm volatile("mbarrier.arrive.expect_tx.shared.b64 _, [%0], %1;"
                 :: "r"(mbar), "r"(bytes * 10u) : "memory");
#pragma unroll
    for (int k = 0; k < 9; k++) {
        const float* src = wgt + ((size_t)(img * 9 + k) << 14) + rlo * W;
        bulk_g2s(ws + (u32)(k * RROWS + droff) * (W * 4), src, bytes, mbar);
    }
    bulk_g2s(xs + (u32)droff * (W * 4), x + ((size_t)img << 14) + rlo * W, bytes, mbar);
}

__global__ __launch_bounds__(512, 1)
void diffusion_persist_kernel(const float* __restrict__ x,
                              const float* __restrict__ wgt,
                              float* __restrict__ out)
{
    extern __shared__ char smem[];
    float (*buf)[SROWS][W] = (float (*)[SROWS][W])(smem + OFF_BUF);
    const float* wsp = (const float*)(smem + OFF_WS);
    const float* xsp = (const float*)(smem + OFF_XS);
    const u32 mbar = s2u(smem + OFF_MBAR);
    const u32 ws_a = s2u(smem + OFF_WS);
    const u32 xs_a = s2u(smem + OFF_XS);

    const int tid  = threadIdx.x;
    const int lane = tid & 31;
    const int warp = tid >> 5;          // 0..15; owns region rows 2g, 2g+1
    const int col0 = lane << 2;
    const int g2   = warp * 2;

    // one-time init: guard rows (region rows -1 and 32 -> zero forever), mbar
    if (tid < 128) {
        int b = tid >> 6, r = (tid >> 5) & 1;
        *(float4*)&buf[b][r ? (SROWS - 1) : 0][col0] = make_float4(0.f, 0.f, 0.f, 0.f);
    }
    if (tid == 0) {
        asm volatile("mbarrier.init.shared.b64 [%0], 1;" :: "r"(mbar) : "memory");
    }
    __syncthreads();

    int t = blockIdx.x;
    const int stride = gridDim.x;
    if (tid == 0 && t < NT) issue_prefetch(t, x, wgt, ws_a, xs_a, mbar);
    u32 ph = 0;

    for (; t < NT; t += stride) {
        mbar_wait(mbar, ph); ph ^= 1u;

        const int img = t >> 3;
        const int t0  = (t & 7) * TH;

        // ---- tile prologue: weights staging -> normalized packed registers
        u64 Wp[2][3][6];
        float4 y0, y1;
#pragma unroll
        for (int ro = 0; ro < 2; ro++) {
            const int rr   = g2 + ro;
            const int grow = t0 - 8 + rr;
            const bool rv  = ((unsigned)grow < (unsigned)H);
            float aa[9][4];
            if (rv) {
                float s0 = 0.f, s1 = 0.f, s2 = 0.f, s3 = 0.f;
#pragma unroll
                for (int k = 0; k < 9; k++) {
                    float4 tv = *(const float4*)&wsp[(k * RROWS + rr) * W + col0];
                    aa[k][0] = fabsf(tv.x); aa[k][1] = fabsf(tv.y);
                    aa[k][2] = fabsf(tv.z); aa[k][3] = fabsf(tv.w);
                    s0 += aa[k][0]; s1 += aa[k][1]; s2 += aa[k][2]; s3 += aa[k][3];
                }
                const float i0 = __fdividef(1.f, s0), i1 = __fdividef(1.f, s1);
                const float i2 = __fdividef(1.f, s2), i3 = __fdividef(1.f, s3);
#pragma unroll
                for (int k = 0; k < 9; k++) {
                    aa[k][0] *= i0; aa[k][1] *= i1; aa[k][2] *= i2; aa[k][3] *= i3;
                }
                // fold image left/right zero padding into lane-edge weights
                if (lane == 0)  { aa[0][0] = 0.f; aa[3][0] = 0.f; aa[6][0] = 0.f; }
                if (lane == 31) { aa[2][3] = 0.f; aa[5][3] = 0.f; aa[8][3] = 0.f; }
            } else {
#pragma unroll
                for (int k = 0; k < 9; k++) {
                    aa[k][0] = 0.f; aa[k][1] = 0.f; aa[k][2] = 0.f; aa[k][3] = 0.f;
                }
            }
#pragma unroll
            for (int ki = 0; ki < 3; ki++) {
                Wp[ro][ki][0] = pk(aa[ki * 3 + 0][0], aa[ki * 3 + 0][1]);
                Wp[ro][ki][1] = pk(aa[ki * 3 + 1][0], aa[ki * 3 + 1][1]);
                Wp[ro][ki][2] = pk(aa[ki * 3 + 2][0], aa[ki * 3 + 2][1]);
                Wp[ro][ki][3] = pk(aa[ki * 3 + 0][2], aa[ki * 3 + 0][3]);
                Wp[ro][ki][4] = pk(aa[ki * 3 + 1][2], aa[ki * 3 + 1][3]);
                Wp[ro][ki][5] = pk(aa[ki * 3 + 2][2], aa[ki * 3 + 2][3]);
            }
            // x init (zero outside the image)
            float4 xv = make_float4(0.f, 0.f, 0.f, 0.f);
            if (rv) xv = *(const float4*)&xsp[rr * W + col0];
            if (ro == 0) y0 = xv; else y1 = xv;
            *(float4*)&buf[0][rr + 1][col0] = xv;
        }
        __syncthreads();   // staging consumed + buf[0] published

        // prefetch next tile (overlaps the 8-step loop)
        if (tid == 0 && t + stride < NT)
            issue_prefetch(t + stride, x, wgt, ws_a, xs_a, mbar);

        // ---- 8 fused steps
#pragma unroll
        for (int s = 0; s < STEPS; s++) {
            const int cb = s & 1;
            float4 va = *(const float4*)&buf[cb][g2][col0];      // region row 2g-1
            float4 vb = *(const float4*)&buf[cb][g2 + 3][col0];  // region row 2g+2

            const float xlA = shup(va.w), xrA = shdn(va.x);
            const float xl0 = shup(y0.w), xr0 = shdn(y0.x);
            const float xl1 = shup(y1.w), xr1 = shdn(y1.x);
            const float xlB = shup(vb.w), xrB = shdn(vb.x);

            u64 n001 = 0ull, n023 = 0ull, n101 = 0ull, n123 = 0ull;
            {
                P5 pA = mkP(xlA, va.x, va.y, va.z, va.w, xrA);
                accrow(n001, n023, Wp[0][0], pA);
            }
            {
                P5 p0 = mkP(xl0, y0.x, y0.y, y0.z, y0.w, xr0);
                accrow(n001, n023, Wp[0][1], p0);
                accrow(n101, n123, Wp[1][0], p0);
            }
            {
                P5 p1 = mkP(xl1, y1.x, y1.y, y1.z, y1.w, xr1);
                accrow(n001, n023, Wp[0][2], p1);
                accrow(n101, n123, Wp[1][1], p1);
            }
            {
                P5 pB = mkP(xlB, vb.x, vb.y, vb.z, vb.w, xrB);
                accrow(n101, n123, Wp[1][2], pB);
            }
            upk(n001, y0.x, y0.y); upk(n023, y0.z, y0.w);
            upk(n101, y1.x, y1.y); upk(n123, y1.z, y1.w);

            if (s < STEPS - 1) {
                const int nb = cb ^ 1;
                *(float4*)&buf[nb][g2 + 1][col0] = y0;
                *(float4*)&buf[nb][g2 + 2][col0] = y1;
                __syncthreads();
            }
        }

        // ---- output: warps 4..11 hold the 16 exact rows (region rows 8..23)
        if ((unsigned)(warp - 4) < 8u) {
            float* ob = out + (size_t)img * IMG + (t0 + g2 - 8) * W + col0;
            *(float4*)ob       = y0;
            *(float4*)(ob + W) = y1;
        }
        // next iteration: prologue writes buf[0] only (safe: last buf[0] read
        // was step 6, fenced by its barrier); buf[1] protected by the
        // post-prologue __syncthreads.
    }
}

extern "C" void kernel_launch(void* const* d_in, const int* in_sizes, int n_in,
                              void* d_out, int out_size)
{
    const float* x   = (const float*)d_in[0];
    const float* wgt = (const float*)d_in[1];
    float* out       = (float*)d_out;

    int sms = 148;
    cudaDeviceGetAttribute(&sms, cudaDevAttrMultiProcessorCount, 0);
    if (sms < 1) sms = 148;
    if (sms > NT) sms = NT;

    cudaFuncSetAttribute(diffusion_persist_kernel,
                         cudaFuncAttributeMaxDynamicSharedMemorySize, SMEM_TOTAL);
    diffusion_persist_kernel<<<sms, 512, SMEM_TOTAL>>>(x, wgt, out);
}